// round 5
// baseline (speedup 1.0000x reference)
#include <cuda_runtime.h>

#define SDIM   128
#define DIM    480           // 128 + 64*3 + 32*5
#define VN4    88            // vector region float4 per row
#define EPS    1e-5f

// Reconstruct the two segment norms owned (partially) by this thread and
// normalize its 4 floats. tid is the row-local vector thread id (0..87).
// sA/sB: this thread's partial sum left/right of its segment boundary.
// *n = from lane+1, *p = from lane-1 (already warp-boundary patched).
__device__ __forceinline__ float4 finish_vec(
    int tid, float4 v,
    float sA, float qA, float sB, float qB,
    float sAn, float qAn, float sBp, float qBp, float sAp, float qAp)
{
    float sumL, sqL, sumR, sqR, invn;
    int cL;
    if (tid < 48) {                       // segments of 3, floats 4t..4t+3
        int r3 = tid % 3;                 // (4t) mod 3 == t mod 3
        cL = 3 - r3;                      // elems in left segment
        sumL = sA + (r3 ? sBp : 0.0f);
        sqL  = qA + (r3 ? qBp : 0.0f);
        sumR = sB + (r3 == 2 ? 0.0f : sAn);
        sqR  = qB + (r3 == 2 ? 0.0f : qAn);
        invn = (1.0f / 3.0f);
    } else {                              // segments of 5
        int r5 = (4 * tid - 192) % 5;
        cL = r5 ? (5 - r5) : 4;
        float pS = (r5 == 0) ? sAn : (r5 == 4 ? sAp : sBp);
        float pQ = (r5 == 0) ? qAn : (r5 == 4 ? qAp : qBp);
        sumL = sA + pS;
        sqL  = qA + pQ;
        sumR = sB + sAn;                  // valid only when r5>=2 (else unused)
        sqR  = qB + qAn;
        invn = 0.2f;
    }
    float mL = sumL * invn;
    float rL = rsqrtf(sqL * invn - mL * mL + EPS);
    float mR = sumR * invn;
    float rR = rsqrtf(sqR * invn - mR * mR + EPS);
    float4 o;
    o.x = (v.x - mL) * rL;                            // j=0 always left
    o.y = (1 < cL) ? (v.y - mL) * rL : (v.y - mR) * rR;
    o.z = (2 < cL) ? (v.z - mL) * rL : (v.z - mR) * rR;
    o.w = (3 < cL) ? (v.w - mL) * rL : (v.w - mR) * rR;
    return o;
}

__global__ __launch_bounds__(128) void eln_kernel(
    const float* __restrict__ x,
    const float* __restrict__ weight,
    const float* __restrict__ bias,
    float* __restrict__ out)
{
    __shared__ float red[16];    // scalar-LN warp partials: sum0 sq0 sum1 sq1
    __shared__ float xch[2][8];  // cross-warp segment-boundary exchange

    const int tid = threadIdx.x;
    const long long base0 = (long long)blockIdx.x * (2 * DIM);
    const long long base1 = base0 + DIM;

    // ---- batch ALL global loads for both rows up front ----
    const float w  = __ldg(&weight[tid]);
    const float bb = __ldg(&bias[tid]);
    const float s0 = x[base0 + tid];
    const float s1 = x[base1 + tid];
    float4 v0 = make_float4(0.f, 0.f, 0.f, 0.f);
    float4 v1 = make_float4(0.f, 0.f, 0.f, 0.f);
    if (tid < VN4) {
        v0 = ((const float4*)(x + base0 + SDIM))[tid];
        v1 = ((const float4*)(x + base1 + SDIM))[tid];
    }

    // ---- per-thread split partials (left/right of segment boundary) ----
    int cL = 4;
    if (tid < 48) cL = 3 - tid % 3;
    else if (tid < VN4) { int r5 = (4 * tid - 192) % 5; cL = r5 ? (5 - r5) : 4; }

    float sA0 = 0.f, qA0 = 0.f, sB0 = 0.f, qB0 = 0.f;
    float sA1 = 0.f, qA1 = 0.f, sB1 = 0.f, qB1 = 0.f;
    {
        float e;
        e = v0.x;                { sA0 += e; qA0 += e * e; }             // j=0 always left
        e = v0.y; if (1 < cL)    { sA0 += e; qA0 += e * e; } else { sB0 += e; qB0 += e * e; }
        e = v0.z; if (2 < cL)    { sA0 += e; qA0 += e * e; } else { sB0 += e; qB0 += e * e; }
        e = v0.w; if (3 < cL)    { sA0 += e; qA0 += e * e; } else { sB0 += e; qB0 += e * e; }
        e = v1.x;                { sA1 += e; qA1 += e * e; }
        e = v1.y; if (1 < cL)    { sA1 += e; qA1 += e * e; } else { sB1 += e; qB1 += e * e; }
        e = v1.z; if (2 < cL)    { sA1 += e; qA1 += e * e; } else { sB1 += e; qB1 += e * e; }
        e = v1.w; if (3 < cL)    { sA1 += e; qA1 += e * e; } else { sB1 += e; qB1 += e * e; }
    }

    // ---- cross-warp boundary exchange writes ----
    // t=31 (r3=1) needs t=32's sA as sAn;  t=32 (r3=2) needs t=31's sB as sBp.
    // t=63 (r5=0) needs t=64's sA as sAn;  t=64 (r5=4) needs t=63's sA as sAp.
    if (tid == 32) { xch[0][0] = sA0; xch[0][1] = qA0; xch[1][0] = sA1; xch[1][1] = qA1; }
    if (tid == 31) { xch[0][2] = sB0; xch[0][3] = qB0; xch[1][2] = sB1; xch[1][3] = qB1; }
    if (tid == 64) { xch[0][4] = sA0; xch[0][5] = qA0; xch[1][4] = sA1; xch[1][5] = qA1; }
    if (tid == 63) { xch[0][6] = sA0; xch[0][7] = qA0; xch[1][6] = sA1; xch[1][7] = qA1; }

    // ---- scalar layernorm warp partials ----
    float sum0 = s0, sq0 = s0 * s0;
    float sum1 = s1, sq1 = s1 * s1;
    #pragma unroll
    for (int o = 16; o; o >>= 1) {
        sum0 += __shfl_xor_sync(0xFFFFFFFFu, sum0, o);
        sq0  += __shfl_xor_sync(0xFFFFFFFFu, sq0,  o);
        sum1 += __shfl_xor_sync(0xFFFFFFFFu, sum1, o);
        sq1  += __shfl_xor_sync(0xFFFFFFFFu, sq1,  o);
    }
    const int w5 = tid >> 5;
    if ((tid & 31) == 0) {
        red[w5] = sum0; red[4 + w5] = sq0;
        red[8 + w5] = sum1; red[12 + w5] = sq1;
    }
    __syncthreads();   // the ONLY barrier

    // ---- scalar outputs ----
    {
        const float m0 = (red[0] + red[1] + red[2] + red[3]) * (1.0f / 128.0f);
        const float r0 = rsqrtf((red[4] + red[5] + red[6] + red[7]) * (1.0f / 128.0f) - m0 * m0 + EPS);
        const float m1 = (red[8] + red[9] + red[10] + red[11]) * (1.0f / 128.0f);
        const float r1 = rsqrtf((red[12] + red[13] + red[14] + red[15]) * (1.0f / 128.0f) - m1 * m1 + EPS);
        out[base0 + tid] = (s0 - m0) * r0 * w + bb;
        out[base1 + tid] = (s1 - m1) * r1 * w + bb;
    }

    // ---- vector region: neighbor shuffles + in-register segment norms ----
    if (tid < 96) {   // warps 0..2 (all lanes participate in shuffles)
        float sAn0 = __shfl_down_sync(0xFFFFFFFFu, sA0, 1);
        float qAn0 = __shfl_down_sync(0xFFFFFFFFu, qA0, 1);
        float sBp0 = __shfl_up_sync  (0xFFFFFFFFu, sB0, 1);
        float qBp0 = __shfl_up_sync  (0xFFFFFFFFu, qB0, 1);
        float sAp0 = __shfl_up_sync  (0xFFFFFFFFu, sA0, 1);
        float qAp0 = __shfl_up_sync  (0xFFFFFFFFu, qA0, 1);
        float sAn1 = __shfl_down_sync(0xFFFFFFFFu, sA1, 1);
        float qAn1 = __shfl_down_sync(0xFFFFFFFFu, qA1, 1);
        float sBp1 = __shfl_up_sync  (0xFFFFFFFFu, sB1, 1);
        float qBp1 = __shfl_up_sync  (0xFFFFFFFFu, qB1, 1);
        float sAp1 = __shfl_up_sync  (0xFFFFFFFFu, sA1, 1);
        float qAp1 = __shfl_up_sync  (0xFFFFFFFFu, qA1, 1);

        // patch the two cross-warp segment boundaries from smem
        if (tid == 31) { sAn0 = xch[0][0]; qAn0 = xch[0][1]; sAn1 = xch[1][0]; qAn1 = xch[1][1]; }
        if (tid == 32) { sBp0 = xch[0][2]; qBp0 = xch[0][3]; sBp1 = xch[1][2]; qBp1 = xch[1][3]; }
        if (tid == 63) { sAn0 = xch[0][4]; qAn0 = xch[0][5]; sAn1 = xch[1][4]; qAn1 = xch[1][5]; }
        if (tid == 64) { sAp0 = xch[0][6]; qAp0 = xch[0][7]; sAp1 = xch[1][6]; qAp1 = xch[1][7]; }

        if (tid < VN4) {
            float4 o0 = finish_vec(tid, v0, sA0, qA0, sB0, qB0,
                                   sAn0, qAn0, sBp0, qBp0, sAp0, qAp0);
            float4 o1 = finish_vec(tid, v1, sA1, qA1, sB1, qB1,
                                   sAn1, qAn1, sBp1, qBp1, sAp1, qAp1);
            ((float4*)(out + base0 + SDIM))[tid] = o0;
            ((float4*)(out + base1 + SDIM))[tid] = o1;
        }
    }
}

extern "C" void kernel_launch(void* const* d_in, const int* in_sizes, int n_in,
                              void* d_out, int out_size)
{
    const float* x      = (const float*)d_in[0];
    const float* weight = (const float*)d_in[1];
    const float* bias   = (const float*)d_in[2];
    float* out = (float*)d_out;

    const int n_rows = in_sizes[0] / DIM;   // 262144
    eln_kernel<<<n_rows / 2, 128>>>(x, weight, bias, out);
}

// round 6
// speedup vs baseline: 1.2129x; 1.2129x over previous
#include <cuda_runtime.h>

#define SDIM   128
#define DIM    480           // 128 + 64*3 + 32*5
#define VDIM   352
#define VN4    88            // vector region float4 per row
#define EPS    1e-5f

__global__ __launch_bounds__(128) void eln_kernel(
    const float* __restrict__ x,
    const float* __restrict__ weight,
    const float* __restrict__ bias,
    float* __restrict__ out)
{
    __shared__ float  val[2][VDIM];   // raw vector values (transposed access)
    __shared__ float2 st[2][96];      // per-segment {mean, rinv}
    __shared__ float  red[16];        // scalar-LN warp partials

    const int tid = threadIdx.x;
    const long long base0 = (long long)blockIdx.x * (2 * DIM);
    const long long base1 = base0 + DIM;

    // ---- batch ALL global loads for both rows up front (max MLP) ----
    const float w  = __ldg(&weight[tid]);
    const float bb = __ldg(&bias[tid]);
    const float s0 = x[base0 + tid];
    const float s1 = x[base1 + tid];
    float4 v0, v1;
    if (tid < VN4) {
        v0 = ((const float4*)(x + base0 + SDIM))[tid];
        v1 = ((const float4*)(x + base1 + SDIM))[tid];
        ((float4*)val[0])[tid] = v0;
        ((float4*)val[1])[tid] = v1;
    }

    // ---- scalar layernorm warp partials ----
    float sum0 = s0, sq0 = s0 * s0;
    float sum1 = s1, sq1 = s1 * s1;
    #pragma unroll
    for (int o = 16; o; o >>= 1) {
        sum0 += __shfl_xor_sync(0xFFFFFFFFu, sum0, o);
        sq0  += __shfl_xor_sync(0xFFFFFFFFu, sq0,  o);
        sum1 += __shfl_xor_sync(0xFFFFFFFFu, sum1, o);
        sq1  += __shfl_xor_sync(0xFFFFFFFFu, sq1,  o);
    }
    const int w5 = tid >> 5;
    if ((tid & 31) == 0) {
        red[w5] = sum0; red[4 + w5] = sq0;
        red[8 + w5] = sum1; red[12 + w5] = sq1;
    }
    __syncthreads();

    // ---- segment owners: compute stats only, publish {mean, rinv} ----
    if (tid < 64) {
        // segment of 3, id = tid (strided LDS, stride 3: conflict-free)
        #pragma unroll
        for (int rr = 0; rr < 2; rr++) {
            const float* p = &val[rr][3 * tid];
            float a = p[0], b = p[1], c = p[2];
            float m = (a + b + c) * (1.0f / 3.0f);
            float da = a - m, db = b - m, dc = c - m;
            float r = rsqrtf((da * da + db * db + dc * dc) * (1.0f / 3.0f) + EPS);
            st[rr][tid] = make_float2(m, r);
        }
    } else if (tid < 96) {
        // segment of 5, id = 64 + (tid-64) (stride 5: conflict-free)
        const int g = tid - 64;
        #pragma unroll
        for (int rr = 0; rr < 2; rr++) {
            const float* p = &val[rr][192 + 5 * g];
            float a = p[0], b = p[1], c = p[2], d = p[3], e = p[4];
            float m = (a + b + c + d + e) * 0.2f;
            float da = a - m, db = b - m, dc = c - m, dd = d - m, de = e - m;
            float r = rsqrtf((da * da + db * db + dc * dc + dd * dd + de * de) * 0.2f + EPS);
            st[rr][64 + g] = make_float2(m, r);
        }
    }

    // ---- scalar outputs (no dependents; overlaps with stats path) ----
    {
        const float m0 = (red[0] + red[1] + red[2] + red[3]) * (1.0f / 128.0f);
        const float r0 = rsqrtf((red[4] + red[5] + red[6] + red[7]) * (1.0f / 128.0f) - m0 * m0 + EPS);
        const float m1 = (red[8] + red[9] + red[10] + red[11]) * (1.0f / 128.0f);
        const float r1 = rsqrtf((red[12] + red[13] + red[14] + red[15]) * (1.0f / 128.0f) - m1 * m1 + EPS);
        out[base0 + tid] = (s0 - m0) * r0 * w + bb;
        out[base1 + tid] = (s1 - m1) * r1 * w + bb;
    }
    __syncthreads();

    // ---- normalize own float4 in registers from published stats ----
    if (tid < VN4) {
        int g0, cL;
        if (tid < 48) {
            g0 = (4 * tid) / 3;          // first overlapping segment
            cL = 3 - tid % 3;            // elems of float4 in left segment (1..3)
        } else {
            int u  = 4 * tid - 192;      // offset within 5-region
            int r5 = u % 5;
            g0 = 64 + u / 5;
            cL = (r5 <= 1) ? 4 : (5 - r5);
        }
        const bool needR = (cL < 4);

        float2 L0 = st[0][g0];
        float2 L1 = st[1][g0];
        float2 R0 = needR ? st[0][g0 + 1] : L0;
        float2 R1 = needR ? st[1][g0 + 1] : L1;

        float4 o0, o1;
        o0.x = (v0.x - L0.x) * L0.y;
        o0.y = (1 < cL) ? (v0.y - L0.x) * L0.y : (v0.y - R0.x) * R0.y;
        o0.z = (2 < cL) ? (v0.z - L0.x) * L0.y : (v0.z - R0.x) * R0.y;
        o0.w = (3 < cL) ? (v0.w - L0.x) * L0.y : (v0.w - R0.x) * R0.y;
        o1.x = (v1.x - L1.x) * L1.y;
        o1.y = (1 < cL) ? (v1.y - L1.x) * L1.y : (v1.y - R1.x) * R1.y;
        o1.z = (2 < cL) ? (v1.z - L1.x) * L1.y : (v1.z - R1.x) * R1.y;
        o1.w = (3 < cL) ? (v1.w - L1.x) * L1.y : (v1.w - R1.x) * R1.y;

        ((float4*)(out + base0 + SDIM))[tid] = o0;
        ((float4*)(out + base1 + SDIM))[tid] = o1;
    }
}

extern "C" void kernel_launch(void* const* d_in, const int* in_sizes, int n_in,
                              void* d_out, int out_size)
{
    const float* x      = (const float*)d_in[0];
    const float* weight = (const float*)d_in[1];
    const float* bias   = (const float*)d_in[2];
    float* out = (float*)d_out;

    const int n_rows = in_sizes[0] / DIM;   // 262144
    eln_kernel<<<n_rows / 2, 128>>>(x, weight, bias, out);
}

// round 7
// speedup vs baseline: 1.2445x; 1.0260x over previous
#include <cuda_runtime.h>

#define SDIM   128
#define MUL1   64
#define D1     3
#define MUL2   32
#define D2     5
#define VDIM   352           // 64*3 + 32*5
#define DIM    480           // 128 + VDIM
#define NV4    88            // VDIM/4 float4 per row (vector region)
#define EPS    1e-5f

__device__ __forceinline__ float ldcs_f(const float* p) {
    float v;
    asm volatile("ld.global.cs.f32 %0, [%1];" : "=f"(v) : "l"(p));
    return v;
}
__device__ __forceinline__ float4 ldcs_f4(const float4* p) {
    float4 v;
    asm volatile("ld.global.cs.v4.f32 {%0,%1,%2,%3}, [%4];"
                 : "=f"(v.x), "=f"(v.y), "=f"(v.z), "=f"(v.w) : "l"(p));
    return v;
}
__device__ __forceinline__ void stcs_f(float* p, float v) {
    asm volatile("st.global.cs.f32 [%0], %1;" :: "l"(p), "f"(v));
}
__device__ __forceinline__ void stcs_f4(float4* p, float4 v) {
    asm volatile("st.global.cs.v4.f32 [%0], {%1,%2,%3,%4};"
                 :: "l"(p), "f"(v.x), "f"(v.y), "f"(v.z), "f"(v.w));
}

__device__ __forceinline__ void seg_norm(float* __restrict__ vec, int tid)
{
    if (tid < MUL1) {
        float* p = &vec[D1 * tid];
        float a = p[0], b = p[1], c = p[2];
        float sm = (a + b + c) * (1.0f / 3.0f);
        float da = a - sm, db = b - sm, dc = c - sm;
        float r = rsqrtf((da * da + db * db + dc * dc) * (1.0f / 3.0f) + EPS);
        p[0] = da * r; p[1] = db * r; p[2] = dc * r;
    } else if (tid < MUL1 + MUL2) {
        float* p = &vec[MUL1 * D1 + D2 * (tid - MUL1)];
        float a = p[0], b = p[1], c = p[2], d = p[3], e = p[4];
        float sm = (a + b + c + d + e) * (1.0f / 5.0f);
        float da = a - sm, db = b - sm, dc = c - sm, dd = d - sm, de = e - sm;
        float r = rsqrtf((da * da + db * db + dc * dc + dd * dd + de * de) * (1.0f / 5.0f) + EPS);
        p[0] = da * r; p[1] = db * r; p[2] = dc * r; p[3] = dd * r; p[4] = de * r;
    }
}

__global__ __launch_bounds__(128) void eln_kernel(
    const float* __restrict__ x,
    const float* __restrict__ weight,
    const float* __restrict__ bias,
    float* __restrict__ out)
{
    __shared__ float vec0[VDIM];
    __shared__ float vec1[VDIM];
    __shared__ float red[16];    // [0..3] sum0 [4..7] sq0 [8..11] sum1 [12..15] sq1

    const int tid = threadIdx.x;
    const long long base0 = (long long)blockIdx.x * (2 * DIM);
    const long long base1 = base0 + DIM;

    // ---- batch ALL global loads for both rows up front (max MLP) ----
    const float w  = __ldg(&weight[tid]);       // reused across blocks: keep cached
    const float bb = __ldg(&bias[tid]);
    const float s0 = ldcs_f(x + base0 + tid);   // streaming: evict-first
    const float s1 = ldcs_f(x + base1 + tid);
    float4 v0, v1;
    const float4* __restrict__ xin0 = (const float4*)(x + base0 + SDIM);
    const float4* __restrict__ xin1 = (const float4*)(x + base1 + SDIM);
    if (tid < NV4) { v0 = ldcs_f4(xin0 + tid); v1 = ldcs_f4(xin1 + tid); }

    // ---- warp-level stats for both rows, interleaved ----
    float sum0 = s0, sq0 = s0 * s0;
    float sum1 = s1, sq1 = s1 * s1;
    #pragma unroll
    for (int o = 16; o; o >>= 1) {
        sum0 += __shfl_xor_sync(0xFFFFFFFFu, sum0, o);
        sq0  += __shfl_xor_sync(0xFFFFFFFFu, sq0,  o);
        sum1 += __shfl_xor_sync(0xFFFFFFFFu, sum1, o);
        sq1  += __shfl_xor_sync(0xFFFFFFFFu, sq1,  o);
    }
    const int w5 = tid >> 5;
    if ((tid & 31) == 0) {
        red[w5] = sum0; red[4 + w5] = sq0;
        red[8 + w5] = sum1; red[12 + w5] = sq1;
    }
    if (tid < NV4) {
        ((float4*)vec0)[tid] = v0;
        ((float4*)vec1)[tid] = v1;
    }
    __syncthreads();

    // ---- combine partials redundantly (no extra barrier) ----
    const float m0 = (red[0] + red[1] + red[2] + red[3]) * (1.0f / 128.0f);
    const float r0 = rsqrtf((red[4] + red[5] + red[6] + red[7]) * (1.0f / 128.0f) - m0 * m0 + EPS);
    const float m1 = (red[8] + red[9] + red[10] + red[11]) * (1.0f / 128.0f);
    const float r1 = rsqrtf((red[12] + red[13] + red[14] + red[15]) * (1.0f / 128.0f) - m1 * m1 + EPS);

    // ---- scalar outputs straight to global (overlaps segment work) ----
    stcs_f(out + base0 + tid, (s0 - m0) * r0 * w + bb);
    stcs_f(out + base1 + tid, (s1 - m1) * r1 * w + bb);

    // ---- segment norms for both rows (disjoint smem regions) ----
    seg_norm(vec0, tid);
    seg_norm(vec1, tid);
    __syncthreads();

    // ---- vector region stores (coalesced float4, streaming) ----
    float4* __restrict__ xout0 = (float4*)(out + base0 + SDIM);
    float4* __restrict__ xout1 = (float4*)(out + base1 + SDIM);
    if (tid < NV4) {
        stcs_f4(xout0 + tid, ((float4*)vec0)[tid]);
        stcs_f4(xout1 + tid, ((float4*)vec1)[tid]);
    }
}

extern "C" void kernel_launch(void* const* d_in, const int* in_sizes, int n_in,
                              void* d_out, int out_size)
{
    const float* x      = (const float*)d_in[0];
    const float* weight = (const float*)d_in[1];
    const float* bias   = (const float*)d_in[2];
    float* out = (float*)d_out;

    const int n_rows = in_sizes[0] / DIM;   // 262144
    eln_kernel<<<n_rows / 2, 128>>>(x, weight, bias, out);
}

// round 8
// speedup vs baseline: 1.3182x; 1.0593x over previous
#include <cuda_runtime.h>

#define SDIM   128
#define VDIM   352           // 64*3 + 32*5
#define DIM    480
#define RPB    4             // rows per block
#define EPS    1e-5f

__device__ __forceinline__ float4 ldcs_f4(const float4* p) {
    float4 v;
    asm volatile("ld.global.cs.v4.f32 {%0,%1,%2,%3}, [%4];"
                 : "=f"(v.x), "=f"(v.y), "=f"(v.z), "=f"(v.w) : "l"(p));
    return v;
}
__device__ __forceinline__ void stcs_f4(float4* p, float4 v) {
    asm volatile("st.global.cs.v4.f32 [%0], {%1,%2,%3,%4};"
                 :: "l"(p), "f"(v.x), "f"(v.y), "f"(v.z), "f"(v.w));
}

__global__ __launch_bounds__(128) void eln_kernel(
    const float* __restrict__ x,
    const float* __restrict__ weight,
    const float* __restrict__ bias,
    float* __restrict__ out)
{
    __shared__ float vec[RPB][VDIM];   // flat: 4*88 float4

    const int tid  = threadIdx.x;
    const int lane = tid & 31;
    const int wrp  = tid >> 5;
    const long long row0 = (long long)blockIdx.x * RPB;

    // ---- front-batch ALL loads (scalar float4 + 3 vector float4 + w/b) ----
    const float4 w4 = __ldg((const float4*)weight + lane);
    const float4 b4 = __ldg((const float4*)bias   + lane);

    // warp w owns row (row0+w)'s 128-float scalar region, 32 x LDG.128
    const float4 sv = ldcs_f4((const float4*)(x + (row0 + wrp) * DIM) + lane);

    // vector region: 4 rows x 88 float4 = 352, strided by 128 threads
    float4 v[3];
    #pragma unroll
    for (int k = 0; k < 3; k++) {
        int idx = tid + 128 * k;
        if (idx < RPB * 88) {
            int r = idx / 88, j = idx - r * 88;
            v[k] = ldcs_f4((const float4*)(x + (row0 + r) * DIM + SDIM) + j);
        }
    }

    // ---- scalar layernorm: fully warp-local, no barrier ----
    float sum = sv.x + sv.y + sv.z + sv.w;
    float sq  = sv.x * sv.x + sv.y * sv.y + sv.z * sv.z + sv.w * sv.w;
    #pragma unroll
    for (int o = 16; o; o >>= 1) {
        sum += __shfl_xor_sync(0xFFFFFFFFu, sum, o);
        sq  += __shfl_xor_sync(0xFFFFFFFFu, sq,  o);
    }
    const float m = sum * (1.0f / 128.0f);
    const float rs = rsqrtf(sq * (1.0f / 128.0f) - m * m + EPS);
    float4 so;
    so.x = (sv.x - m) * rs * w4.x + b4.x;
    so.y = (sv.y - m) * rs * w4.y + b4.y;
    so.z = (sv.z - m) * rs * w4.z + b4.z;
    so.w = (sv.w - m) * rs * w4.w + b4.w;
    stcs_f4((float4*)(out + (row0 + wrp) * DIM) + lane, so);

    // ---- stage vector region into smem (conflict-free STS.128) ----
    #pragma unroll
    for (int k = 0; k < 3; k++) {
        int idx = tid + 128 * k;
        if (idx < RPB * 88) ((float4*)vec)[idx] = v[k];
    }
    __syncthreads();

    // ---- segment norms: 4 rows x 96 segments = 384, 3 per thread ----
    #pragma unroll
    for (int k = 0; k < 3; k++) {
        int s = tid + 128 * k;            // 0..383, always valid
        int r = s / 96, k96 = s - r * 96;
        if (k96 < 64) {
            float* p = &vec[r][3 * k96];
            float a = p[0], b = p[1], c = p[2];
            float sm = (a + b + c) * (1.0f / 3.0f);
            float da = a - sm, db = b - sm, dc = c - sm;
            float rr = rsqrtf((da * da + db * db + dc * dc) * (1.0f / 3.0f) + EPS);
            p[0] = da * rr; p[1] = db * rr; p[2] = dc * rr;
        } else {
            float* p = &vec[r][192 + 5 * (k96 - 64)];
            float a = p[0], b = p[1], c = p[2], d = p[3], e = p[4];
            float sm = (a + b + c + d + e) * 0.2f;
            float da = a - sm, db = b - sm, dc = c - sm, dd = d - sm, de = e - sm;
            float rr = rsqrtf((da * da + db * db + dc * dc + dd * dd + de * de) * 0.2f + EPS);
            p[0] = da * rr; p[1] = db * rr; p[2] = dc * rr; p[3] = dd * rr; p[4] = de * rr;
        }
    }
    __syncthreads();

    // ---- vector region stores (coalesced STG.128) ----
    #pragma unroll
    for (int k = 0; k < 3; k++) {
        int idx = tid + 128 * k;
        if (idx < RPB * 88) {
            int r = idx / 88, j = idx - r * 88;
            stcs_f4((float4*)(out + (row0 + r) * DIM + SDIM) + j, ((float4*)vec)[idx]);
        }
    }
}

extern "C" void kernel_launch(void* const* d_in, const int* in_sizes, int n_in,
                              void* d_out, int out_size)
{
    const float* x      = (const float*)d_in[0];
    const float* weight = (const float*)d_in[1];
    const float* bias   = (const float*)d_in[2];
    float* out = (float*)d_out;

    const int n_rows = in_sizes[0] / DIM;   // 262144
    eln_kernel<<<n_rows / RPB, 128>>>(x, weight, bias, out);
}